// round 8
// baseline (speedup 1.0000x reference)
#include <cuda_runtime.h>
#include <cstdint>

#define BATCH 4
#define SEQ   2048
#define CH    1024
#define NHEAD 16
#define HDIM  64

// Scratch (allocation-free rule: __device__ globals).
// q,k: [b,h,t,d]; v: [b,h,d,t] (transposed for PV ldmatrix).
__device__ float g_q[BATCH * NHEAD * SEQ * HDIM];
__device__ float g_k[BATCH * NHEAD * SEQ * HDIM];
__device__ float g_v[BATCH * NHEAD * HDIM * SEQ];
__device__ float g_att[BATCH * SEQ * CH];        // [b,t,c], tf32-rounded
__device__ float g_x [BATCH * SEQ * CH];         // x, tf32-rounded
__device__ float g_wa[3 * CH * CH];              // w_attn^T: [3072][1024], tf32
__device__ float g_wp[CH * CH];                  // w_proj^T: [1024][1024], tf32

__device__ __forceinline__ float to_tf32(float x) {
    float r;
    asm("cvt.rna.tf32.f32 %0, %1;" : "=f"(r) : "f"(x));
    return r;
}

#define MMA_TF32(d, a, b)                                                  \
    asm volatile(                                                          \
        "mma.sync.aligned.m16n8k8.row.col.f32.tf32.tf32.f32 "              \
        "{%0,%1,%2,%3},{%4,%5,%6,%7},{%8,%9},{%0,%1,%2,%3};"               \
        : "+f"((d)[0]), "+f"((d)[1]), "+f"((d)[2]), "+f"((d)[3])           \
        : "r"((a)[0]), "r"((a)[1]), "r"((a)[2]), "r"((a)[3]),              \
          "r"((b)[0]), "r"((b)[1]))

// ldmatrix x4 on b16 8x8 tiles == 8x4 fp32 blocks (tf32 fragment layout).
#define LDM_X4(r, addr)                                                    \
    asm volatile("ldmatrix.sync.aligned.m8n8.x4.shared.b16 "               \
                 "{%0,%1,%2,%3}, [%4];"                                    \
                 : "=r"((r)[0]), "=r"((r)[1]), "=r"((r)[2]), "=r"((r)[3])  \
                 : "r"(addr))

#define CP_ASYNC16(dst_u32, src_ptr)                                       \
    asm volatile("cp.async.cg.shared.global [%0], [%1], 16;"               \
                 :: "r"(dst_u32), "l"(src_ptr))
#define CP_COMMIT() asm volatile("cp.async.commit_group;")
#define CP_WAIT(N)  asm volatile("cp.async.wait_group %0;" :: "n"(N))

__device__ __forceinline__ uint32_t smem_u32(const void* p) {
    return (uint32_t)__cvta_generic_to_shared(p);
}

// ---------------------------------------------------------------------------
// Prologue converts
// ---------------------------------------------------------------------------
__global__ void cvt_x_kernel(const float* __restrict__ src, int n4)
{
    int i = blockIdx.x * blockDim.x + threadIdx.x;
    if (i < n4) {
        float4 v = reinterpret_cast<const float4*>(src)[i];
        v.x = to_tf32(v.x); v.y = to_tf32(v.y);
        v.z = to_tf32(v.z); v.w = to_tf32(v.w);
        reinterpret_cast<float4*>(g_x)[i] = v;
    }
}

// Transpose + tf32-round weights: src [CH][N] -> dst [N][CH]
__global__ void cvt_T_kernel(const float* __restrict__ src, int sel, int N)
{
    __shared__ float tile[32][33];
    float* dst = (sel == 1) ? g_wa : g_wp;
    int n0 = blockIdx.x * 32, k0 = blockIdx.y * 32;
    int tx = threadIdx.x, ty = threadIdx.y;  // 32 x 8
#pragma unroll
    for (int i = 0; i < 4; i++)
        tile[ty + 8 * i][tx] = src[(size_t)(k0 + ty + 8 * i) * N + n0 + tx];
    __syncthreads();
#pragma unroll
    for (int i = 0; i < 4; i++)
        dst[(size_t)(n0 + ty + 8 * i) * CH + k0 + tx] = to_tf32(tile[tx][ty + 8 * i]);
}

// ---------------------------------------------------------------------------
// TF32 GEMM core: block 128x128, BK=32, 8 warps (2x4), warp tile 64x32.
// 3-stage cp.async pipeline, ONE barrier per slab; next-slab loads are
// interleaved with the kq compute steps (smoothed LSU pressure).
// ---------------------------------------------------------------------------
#define GS 36                      // smem row stride (floats)
#define GBUF (128 * GS)            // floats per buffer
#define NSTAGE 3
#define GEMM_SMEM (2 * NSTAGE * GBUF * (int)sizeof(float))   // 110592 B

__device__ __forceinline__ void gemm_issue_loads(
    const float* __restrict__ A, const float* __restrict__ B,
    int m0, int n0, int k0, uint32_t sA, uint32_t sB, int tid)
{
#pragma unroll
    for (int it = 0; it < 4; it++) {
        int idx = it * 256 + tid;
        int row = idx >> 3, c = idx & 7;
        CP_ASYNC16(sA + row * (GS * 4) + c * 16,
                   A + (size_t)(m0 + row) * CH + k0 + c * 4);
    }
#pragma unroll
    for (int it = 0; it < 4; it++) {
        int idx = it * 256 + tid;
        int row = idx >> 3, c = idx & 7;
        CP_ASYNC16(sB + row * (GS * 4) + c * 16,
                   B + (size_t)(n0 + row) * CH + k0 + c * 4);
    }
}

__device__ __forceinline__ void tf32_gemm_tile(
    const float* __restrict__ A, const float* __restrict__ B,
    int m0, int n0,
    float acc[4][4][4],
    uint32_t sbase, int tid)
{
    const int lane  = tid & 31;
    const int wid   = tid >> 5;
    const int wm    = wid & 1;
    const int wn    = wid >> 1;
    const int lane8 = lane & 7;
    const int laneh = (lane >> 3) & 1;
    const int laneq = lane >> 4;

    const uint32_t sA0 = sbase;
    const uint32_t sB0 = sbase + NSTAGE * GBUF * 4;

    // per-lane ldmatrix offsets (bytes, within a buffer)
    const uint32_t a_lm =
        ((wm * 64 + lane8 + laneh * 8) * GS + laneq * 4) * 4;
    const uint32_t b_lm =
        ((wn * 32 + lane8) * GS + (lane >> 3) * 4) * 4;

    // Prologue: stages 0 and 1 in flight
    gemm_issue_loads(A, B, m0, n0, 0, sA0, sB0, tid);
    CP_COMMIT();
    gemm_issue_loads(A, B, m0, n0, 32, sA0 + GBUF * 4, sB0 + GBUF * 4, tid);
    CP_COMMIT();

    const int nk = CH / 32;
    int stage = 0;
    for (int ki = 0; ki < nk; ki++) {
        if (ki + 1 < nk) { CP_WAIT(1); } else { CP_WAIT(0); }
        __syncthreads();   // slab ki visible; all warps done with slab ki-1

        const uint32_t Ab = sA0 + stage * GBUF * 4;
        const uint32_t Bb = sB0 + stage * GBUF * 4;

        // prefetch targets for slab ki+2 (the stage vacated at ki-1)
        const bool pre = (ki + 2 < nk);
        int ns = stage + 2; if (ns >= NSTAGE) ns -= NSTAGE;
        const uint32_t nA = sA0 + ns * GBUF * 4;
        const uint32_t nB = sB0 + ns * GBUF * 4;
        const int pk0 = (ki + 2) * 32;

        uint32_t bf[4][4];
#pragma unroll
        for (int kq = 0; kq < 4; kq++) {
            if ((kq & 1) == 0) {
#pragma unroll
                for (int nt = 0; nt < 4; nt++)
                    LDM_X4(bf[nt], Bb + b_lm + nt * (8 * GS * 4) + (kq >> 1) * 64);
            }
#pragma unroll
            for (int mt = 0; mt < 4; mt++) {
                uint32_t af[4];
                LDM_X4(af, Ab + a_lm + mt * (16 * GS * 4) + kq * 32);
#pragma unroll
                for (int nt = 0; nt < 4; nt++)
                    MMA_TF32(acc[mt][nt], af, &bf[nt][(kq & 1) * 2]);
            }
            // interleave 1/4 of the next-slab loads after each kq step
            if (pre) {
                int idx = kq * 256 + tid;
                int row = idx >> 3, c = idx & 7;
                CP_ASYNC16(nA + row * (GS * 4) + c * 16,
                           A + (size_t)(m0 + row) * CH + pk0 + c * 4);
                CP_ASYNC16(nB + row * (GS * 4) + c * 16,
                           B + (size_t)(n0 + row) * CH + pk0 + c * 4);
            }
        }
        if (pre) CP_COMMIT();
        stage = (stage + 1 == NSTAGE) ? 0 : stage + 1;
    }
}

// ---------------------------------------------------------------------------
// Kernel 1: QKV GEMM; writes q,k [b,h,t,d] and v [b,h,d,t], tf32-rounded,
// softmax scale folded into q.
// ---------------------------------------------------------------------------
__global__ __launch_bounds__(256) void qkv_gemm_kernel(
    const float* __restrict__ bias)
{
    extern __shared__ float smg[];
    const uint32_t sbase = smem_u32(smg);
    const int tid = threadIdx.x;
    const int m0 = blockIdx.y * 128;
    const int n0 = blockIdx.x * 128;

    float acc[4][4][4];
#pragma unroll
    for (int i = 0; i < 4; i++)
#pragma unroll
        for (int j = 0; j < 4; j++)
#pragma unroll
            for (int q = 0; q < 4; q++) acc[i][j][q] = 0.f;

    tf32_gemm_tile(g_x, g_wa, m0, n0, acc, sbase, tid);

    const int lane = tid & 31;
    const int wid  = tid >> 5;
    const int wm   = wid & 1;
    const int wn   = wid >> 1;
    const int lr   = lane >> 2;
    const int lc   = lane & 3;

    const int sec = n0 >> 10;  // 0=q 1=k 2=v
    const float scale = (sec == 0) ? 0.125f : 1.0f;

#pragma unroll
    for (int mt = 0; mt < 4; mt++) {
        int r0 = m0 + wm * 64 + mt * 16 + lr;
        int bb = r0 >> 11;
        int t  = r0 & (SEQ - 1);
#pragma unroll
        for (int nt = 0; nt < 4; nt++) {
            int c0 = n0 + wn * 32 + nt * 8 + lc * 2;
            float b0 = bias[c0], b1 = bias[c0 + 1];
            int n1 = c0 & (CH - 1);
            int h  = n1 >> 6;
            int d  = n1 & 63;
            float v00 = to_tf32((acc[mt][nt][0] + b0) * scale);
            float v01 = to_tf32((acc[mt][nt][1] + b1) * scale);
            float v10 = to_tf32((acc[mt][nt][2] + b0) * scale);
            float v11 = to_tf32((acc[mt][nt][3] + b1) * scale);
            if (sec < 2) {
                float* dst = (sec == 0) ? g_q : g_k;
                size_t base = ((size_t)((bb * NHEAD + h) * SEQ + t)) * HDIM + d;
                *reinterpret_cast<float2*>(&dst[base]) = make_float2(v00, v01);
                *reinterpret_cast<float2*>(&dst[base + 8 * HDIM]) =
                    make_float2(v10, v11);
            } else {
                // v transposed: [b,h,d,t]
                size_t base = ((size_t)((bb * NHEAD + h) * HDIM + d)) * SEQ + t;
                g_v[base]           = v00;
                g_v[base + SEQ]     = v01;   // d+1
                g_v[base + 8]       = v10;   // t+8
                g_v[base + SEQ + 8] = v11;
            }
        }
    }
}

// ---------------------------------------------------------------------------
// Kernel 3: output projection
// ---------------------------------------------------------------------------
__global__ __launch_bounds__(256) void proj_gemm_kernel(
    const float* __restrict__ bias, float* __restrict__ out)
{
    extern __shared__ float smg[];
    const uint32_t sbase = smem_u32(smg);
    const int tid = threadIdx.x;
    const int m0 = blockIdx.y * 128;
    const int n0 = blockIdx.x * 128;

    float acc[4][4][4];
#pragma unroll
    for (int i = 0; i < 4; i++)
#pragma unroll
        for (int j = 0; j < 4; j++)
#pragma unroll
            for (int q = 0; q < 4; q++) acc[i][j][q] = 0.f;

    tf32_gemm_tile(g_att, g_wp, m0, n0, acc, sbase, tid);

    const int lane = tid & 31;
    const int wid  = tid >> 5;
    const int wm   = wid & 1;
    const int wn   = wid >> 1;
    const int lr   = lane >> 2;
    const int lc   = lane & 3;

#pragma unroll
    for (int mt = 0; mt < 4; mt++) {
        int r0 = m0 + wm * 64 + mt * 16 + lr;
#pragma unroll
        for (int nt = 0; nt < 4; nt++) {
            int c0 = n0 + wn * 32 + nt * 8 + lc * 2;
            float b0 = bias[c0], b1 = bias[c0 + 1];
            *reinterpret_cast<float2*>(&out[(size_t)r0 * CH + c0]) =
                make_float2(acc[mt][nt][0] + b0, acc[mt][nt][1] + b1);
            *reinterpret_cast<float2*>(&out[(size_t)(r0 + 8) * CH + c0]) =
                make_float2(acc[mt][nt][2] + b0, acc[mt][nt][3] + b1);
        }
    }
}

// ---------------------------------------------------------------------------
// Kernel 2: causal flash attention, TF32 mma.sync + ldmatrix fragments,
// cp.async double-buffered K/V, ONE barrier per kv tile (next-tile loads are
// issued after the top barrier, making the bottom buffer-guard redundant).
// Block: 128 q x 64 kv; 8 warps x 16 q rows.
// ---------------------------------------------------------------------------
#define AST 68                     // attention smem row stride (floats)
#define KV_BUF (64 * AST)
#define ATTN_SMEM ((128 * AST + 4 * KV_BUF) * (int)sizeof(float))

__device__ __forceinline__ void attn_issue_kv(
    const float* __restrict__ kp, const float* __restrict__ vp,
    int k0, uint32_t sK, uint32_t sV, int tid)
{
#pragma unroll
    for (int it = 0; it < 4; it++) {
        int idx = it * 256 + tid;
        int row = idx >> 4;
        int c4  = (idx & 15) * 4;
        CP_ASYNC16(sK + row * (AST * 4) + c4 * 4,
                   kp + (size_t)(k0 + row) * HDIM + c4);
        CP_ASYNC16(sV + row * (AST * 4) + c4 * 4,
                   vp + (size_t)row * SEQ + k0 + c4);
    }
}

__global__ __launch_bounds__(256) void attn_kernel()
{
    extern __shared__ float sm[];
    const uint32_t sbase = smem_u32(sm);
    const uint32_t sQs = sbase;
    const uint32_t sKs = sbase + 128 * AST * 4;
    const uint32_t sVs = sKs + 2 * KV_BUF * 4;

    const int tid   = threadIdx.x;
    const int lane  = tid & 31;
    const int wq    = tid >> 5;
    const int lr    = lane >> 2;
    const int lc    = lane & 3;
    const int lane8 = lane & 7;
    const int laneh = (lane >> 3) & 1;
    const int laneq = lane >> 4;

    const int qt = (int)gridDim.x - 1 - (int)blockIdx.x;  // big tiles first
    const int bh = blockIdx.y;
    const int q0 = qt * 128;

    const float* qp = g_q + (size_t)bh * SEQ * HDIM;
    const float* kp = g_k + (size_t)bh * SEQ * HDIM;
    const float* vp = g_v + (size_t)bh * HDIM * SEQ;

    const uint32_t q_lm = sQs +
        ((wq * 16 + lane8 + laneh * 8) * AST + laneq * 4) * 4;
    const uint32_t k_lm = (lane8 * AST + (lane >> 3) * 4) * 4;
    const uint32_t p_lm = ((lane8 + laneh * 8) * AST + laneq * 4) * 4;
    const uint32_t v_lm = ((laneq * 8 + lane8) * AST + laneh * 4) * 4;

    // Prologue: Q tile + first K/V tile in one group
#pragma unroll
    for (int it = 0; it < 8; it++) {
        int idx = it * 256 + tid;
        int row = idx >> 4;
        int c4  = (idx & 15) * 4;
        CP_ASYNC16(sQs + row * (AST * 4) + c4 * 4,
                   qp + (size_t)(q0 + row) * HDIM + c4);
    }
    attn_issue_kv(kp, vp, 0, sKs, sVs, tid);
    CP_COMMIT();

    uint32_t qf[8][4];
    const uint32_t sPt = sQs + wq * 16 * AST * 4;   // per-warp 16x64 slab
    float* Pt = sm + wq * 16 * AST;

    float o[8][4] = {};
    float m0v = -1e30f, m1v = -1e30f;
    float l0v = 0.f, l1v = 0.f;

    const int nkt  = 2 * qt + 2;
    const int r_hi = q0 + wq * 16 + 15;

    for (int kt = 0; kt < nkt; kt++) {
        const int k0 = kt * 64;
        CP_WAIT(0);        // tile kt (and, at kt==0, Q) fully arrived
        __syncthreads();   // all warps done reading buffer (kt+1)&1 from kt-1

        // Issue next tile AFTER the barrier: buffer reuse now provably safe,
        // and the bottom barrier is eliminated.
        if (kt + 1 < nkt) {
            attn_issue_kv(kp, vp, (kt + 1) * 64,
                          sKs + ((kt + 1) & 1) * KV_BUF * 4,
                          sVs + ((kt + 1) & 1) * KV_BUF * 4, tid);
            CP_COMMIT();
        }

        if (kt == 0) {
#pragma unroll
            for (int s = 0; s < 8; s++)
                LDM_X4(qf[s], q_lm + s * 32);
        }

        if (k0 <= r_hi) {
            const uint32_t Kb = sKs + (kt & 1) * KV_BUF * 4;
            const uint32_t Vb = sVs + (kt & 1) * KV_BUF * 4;

            float sacc[8][4];
#pragma unroll
            for (int nt = 0; nt < 8; nt++)
#pragma unroll
                for (int q = 0; q < 4; q++) sacc[nt][q] = 0.f;

#pragma unroll
            for (int s2 = 0; s2 < 4; s2++) {
                uint32_t bf[8][4];
#pragma unroll
                for (int nt = 0; nt < 8; nt++)
                    LDM_X4(bf[nt], Kb + k_lm + nt * (8 * AST * 4) + s2 * 64);
#pragma unroll
                for (int sub = 0; sub < 2; sub++)
#pragma unroll
                    for (int nt = 0; nt < 8; nt++)
                        MMA_TF32(sacc[nt], qf[2 * s2 + sub], &bf[nt][sub * 2]);
            }

            if (kt >= 2 * qt) {
                int r0g = q0 + wq * 16 + lr;
#pragma unroll
                for (int nt = 0; nt < 8; nt++) {
                    int c0g = k0 + nt * 8 + 2 * lc;
                    if (c0g     > r0g)     sacc[nt][0] = -1e30f;
                    if (c0g + 1 > r0g)     sacc[nt][1] = -1e30f;
                    if (c0g     > r0g + 8) sacc[nt][2] = -1e30f;
                    if (c0g + 1 > r0g + 8) sacc[nt][3] = -1e30f;
                }
            }

            float rm0 = -1e30f, rm1 = -1e30f;
#pragma unroll
            for (int nt = 0; nt < 8; nt++) {
                rm0 = fmaxf(rm0, fmaxf(sacc[nt][0], sacc[nt][1]));
                rm1 = fmaxf(rm1, fmaxf(sacc[nt][2], sacc[nt][3]));
            }
            rm0 = fmaxf(rm0, __shfl_xor_sync(0xffffffffu, rm0, 1));
            rm0 = fmaxf(rm0, __shfl_xor_sync(0xffffffffu, rm0, 2));
            rm1 = fmaxf(rm1, __shfl_xor_sync(0xffffffffu, rm1, 1));
            rm1 = fmaxf(rm1, __shfl_xor_sync(0xffffffffu, rm1, 2));

            float mn0 = fmaxf(m0v, rm0);
            float mn1 = fmaxf(m1v, rm1);
            float cr0 = __expf(m0v - mn0);
            float cr1 = __expf(m1v - mn1);
            m0v = mn0; m1v = mn1;

            float rs0 = 0.f, rs1 = 0.f;
#pragma unroll
            for (int nt = 0; nt < 8; nt++) {
                sacc[nt][0] = __expf(sacc[nt][0] - mn0);
                sacc[nt][1] = __expf(sacc[nt][1] - mn0);
                sacc[nt][2] = __expf(sacc[nt][2] - mn1);
                sacc[nt][3] = __expf(sacc[nt][3] - mn1);
                rs0 += sacc[nt][0] + sacc[nt][1];
                rs1 += sacc[nt][2] + sacc[nt][3];
            }
            rs0 += __shfl_xor_sync(0xffffffffu, rs0, 1);
            rs0 += __shfl_xor_sync(0xffffffffu, rs0, 2);
            rs1 += __shfl_xor_sync(0xffffffffu, rs1, 1);
            rs1 += __shfl_xor_sync(0xffffffffu, rs1, 2);
            l0v = l0v * cr0 + rs0;
            l1v = l1v * cr1 + rs1;
#pragma unroll
            for (int nt = 0; nt < 8; nt++) {
                o[nt][0] *= cr0; o[nt][1] *= cr0;
                o[nt][2] *= cr1; o[nt][3] *= cr1;
            }

#pragma unroll
            for (int nt = 0; nt < 8; nt++) {
                *reinterpret_cast<float2*>(&Pt[lr * AST + nt * 8 + 2 * lc]) =
                    make_float2(to_tf32(sacc[nt][0]), to_tf32(sacc[nt][1]));
                *reinterpret_cast<float2*>(&Pt[(lr + 8) * AST + nt * 8 + 2 * lc]) =
                    make_float2(to_tf32(sacc[nt][2]), to_tf32(sacc[nt][3]));
            }
            __syncwarp();

#pragma unroll
            for (int s = 0; s < 8; s++) {
                uint32_t a[4];
                LDM_X4(a, sPt + p_lm + s * 32);
#pragma unroll
                for (int dp = 0; dp < 4; dp++) {
                    uint32_t b[4];
                    LDM_X4(b, Vb + v_lm + dp * (16 * AST * 4) + s * 32);
                    MMA_TF32(o[2 * dp],     a, &b[0]);
                    MMA_TF32(o[2 * dp + 1], a, &b[2]);
                }
            }
            __syncwarp();
        }
        // no bottom barrier: next iteration's top barrier provides the guard
    }

    const int b = bh >> 4, h = bh & 15;
    const int r0g = q0 + wq * 16 + lr;
    const float inv0 = 1.0f / l0v;
    const float inv1 = 1.0f / l1v;
#pragma unroll
    for (int nt = 0; nt < 8; nt++) {
        int cg = h * 64 + nt * 8 + 2 * lc;
        *reinterpret_cast<float2*>(&g_att[(size_t)(b * SEQ + r0g) * CH + cg]) =
            make_float2(to_tf32(o[nt][0] * inv0), to_tf32(o[nt][1] * inv0));
        *reinterpret_cast<float2*>(&g_att[(size_t)(b * SEQ + r0g + 8) * CH + cg]) =
            make_float2(to_tf32(o[nt][2] * inv1), to_tf32(o[nt][3] * inv1));
    }
}

// ---------------------------------------------------------------------------
extern "C" void kernel_launch(void* const* d_in, const int* in_sizes, int n_in,
                              void* d_out, int out_size)
{
    const float* x      = (const float*)d_in[0];
    const float* w_attn = (const float*)d_in[1];
    const float* b_attn = (const float*)d_in[2];
    const float* w_proj = (const float*)d_in[3];
    const float* b_proj = (const float*)d_in[4];
    float* out = (float*)d_out;

    cudaFuncSetAttribute(qkv_gemm_kernel,
                         cudaFuncAttributeMaxDynamicSharedMemorySize, GEMM_SMEM);
    cudaFuncSetAttribute(proj_gemm_kernel,
                         cudaFuncAttributeMaxDynamicSharedMemorySize, GEMM_SMEM);
    cudaFuncSetAttribute(attn_kernel,
                         cudaFuncAttributeMaxDynamicSharedMemorySize, ATTN_SMEM);

    // 0) tf32-round x; transpose+round weights to [N][K]
    cvt_x_kernel<<<(BATCH * SEQ * CH / 4 + 255) / 256, 256>>>(x,
        BATCH * SEQ * CH / 4);
    cvt_T_kernel<<<dim3(3 * CH / 32, CH / 32), dim3(32, 8)>>>(w_attn, 1, 3 * CH);
    cvt_T_kernel<<<dim3(CH / 32, CH / 32), dim3(32, 8)>>>(w_proj, 2, CH);

    // 1) QKV GEMM: grid (3072/128, 8192/128)
    qkv_gemm_kernel<<<dim3(24, 64), 256, GEMM_SMEM>>>(b_attn);

    // 2) Attention: grid (16 q-tiles, B*NH)
    attn_kernel<<<dim3(16, BATCH * NHEAD), 256, ATTN_SMEM>>>();

    // 3) Projection: grid (1024/128, 8192/128)
    proj_gemm_kernel<<<dim3(8, 64), 256, GEMM_SMEM>>>(b_proj, out);
}

// round 9
// speedup vs baseline: 1.0738x; 1.0738x over previous
#include <cuda_runtime.h>
#include <cstdint>

#define BATCH 4
#define SEQ   2048
#define CH    1024
#define NHEAD 16
#define HDIM  64

// Scratch (allocation-free rule: __device__ globals).
// q,k: [b,h,t,d]; v: [b,h,d,t] (transposed for PV ldmatrix).
__device__ float g_q[BATCH * NHEAD * SEQ * HDIM];
__device__ float g_k[BATCH * NHEAD * SEQ * HDIM];
__device__ float g_v[BATCH * NHEAD * HDIM * SEQ];
__device__ float g_att[BATCH * SEQ * CH];        // [b,t,c], tf32-rounded
__device__ float g_x [BATCH * SEQ * CH];         // x, tf32-rounded
__device__ float g_wa[3 * CH * CH];              // w_attn^T: [3072][1024], tf32
__device__ float g_wp[CH * CH];                  // w_proj^T: [1024][1024], tf32

__device__ __forceinline__ float to_tf32(float x) {
    float r;
    asm("cvt.rna.tf32.f32 %0, %1;" : "=f"(r) : "f"(x));
    return r;
}

#define MMA_TF32(d, a, b)                                                  \
    asm volatile(                                                          \
        "mma.sync.aligned.m16n8k8.row.col.f32.tf32.tf32.f32 "              \
        "{%0,%1,%2,%3},{%4,%5,%6,%7},{%8,%9},{%0,%1,%2,%3};"               \
        : "+f"((d)[0]), "+f"((d)[1]), "+f"((d)[2]), "+f"((d)[3])           \
        : "r"((a)[0]), "r"((a)[1]), "r"((a)[2]), "r"((a)[3]),              \
          "r"((b)[0]), "r"((b)[1]))

// ldmatrix x4 on b16 8x8 tiles == 8x4 fp32 blocks (tf32 fragment layout).
#define LDM_X4(r, addr)                                                    \
    asm volatile("ldmatrix.sync.aligned.m8n8.x4.shared.b16 "               \
                 "{%0,%1,%2,%3}, [%4];"                                    \
                 : "=r"((r)[0]), "=r"((r)[1]), "=r"((r)[2]), "=r"((r)[3])  \
                 : "r"(addr))

#define CP_ASYNC16(dst_u32, src_ptr)                                       \
    asm volatile("cp.async.cg.shared.global [%0], [%1], 16;"               \
                 :: "r"(dst_u32), "l"(src_ptr))
#define CP_COMMIT() asm volatile("cp.async.commit_group;")
#define CP_WAIT(N)  asm volatile("cp.async.wait_group %0;" :: "n"(N))

__device__ __forceinline__ uint32_t smem_u32(const void* p) {
    return (uint32_t)__cvta_generic_to_shared(p);
}

// ---------------------------------------------------------------------------
// Prologue converts
// ---------------------------------------------------------------------------
__global__ void cvt_x_kernel(const float* __restrict__ src, int n4)
{
    int i = blockIdx.x * blockDim.x + threadIdx.x;
    if (i < n4) {
        float4 v = reinterpret_cast<const float4*>(src)[i];
        v.x = to_tf32(v.x); v.y = to_tf32(v.y);
        v.z = to_tf32(v.z); v.w = to_tf32(v.w);
        reinterpret_cast<float4*>(g_x)[i] = v;
    }
}

// Transpose + tf32-round weights: src [CH][N] -> dst [N][CH]
__global__ void cvt_T_kernel(const float* __restrict__ src, int sel, int N)
{
    __shared__ float tile[32][33];
    float* dst = (sel == 1) ? g_wa : g_wp;
    int n0 = blockIdx.x * 32, k0 = blockIdx.y * 32;
    int tx = threadIdx.x, ty = threadIdx.y;  // 32 x 8
#pragma unroll
    for (int i = 0; i < 4; i++)
        tile[ty + 8 * i][tx] = src[(size_t)(k0 + ty + 8 * i) * N + n0 + tx];
    __syncthreads();
#pragma unroll
    for (int i = 0; i < 4; i++)
        dst[(size_t)(n0 + ty + 8 * i) * CH + k0 + tx] = to_tf32(tile[tx][ty + 8 * i]);
}

// ---------------------------------------------------------------------------
// TF32 GEMM core: block 128x128, BK=32, 8 warps (2x4), warp tile 64x32.
// 3-stage cp.async pipeline (burst issue after compute, round-7 proven) +
// register double-buffered A fragments (LDSM latency hidden behind mma).
// ---------------------------------------------------------------------------
#define GS 36                      // smem row stride (floats)
#define GBUF (128 * GS)            // floats per buffer
#define NSTAGE 3
#define GEMM_SMEM (2 * NSTAGE * GBUF * (int)sizeof(float))   // 110592 B

__device__ __forceinline__ void gemm_issue_loads(
    const float* __restrict__ A, const float* __restrict__ B,
    int m0, int n0, int k0, uint32_t sA, uint32_t sB, int tid)
{
#pragma unroll
    for (int it = 0; it < 4; it++) {
        int idx = it * 256 + tid;
        int row = idx >> 3, c = idx & 7;
        CP_ASYNC16(sA + row * (GS * 4) + c * 16,
                   A + (size_t)(m0 + row) * CH + k0 + c * 4);
    }
#pragma unroll
    for (int it = 0; it < 4; it++) {
        int idx = it * 256 + tid;
        int row = idx >> 3, c = idx & 7;
        CP_ASYNC16(sB + row * (GS * 4) + c * 16,
                   B + (size_t)(n0 + row) * CH + k0 + c * 4);
    }
}

__device__ __forceinline__ void tf32_gemm_tile(
    const float* __restrict__ A, const float* __restrict__ B,
    int m0, int n0,
    float acc[4][4][4],
    uint32_t sbase, int tid)
{
    const int lane  = tid & 31;
    const int wid   = tid >> 5;
    const int wm    = wid & 1;
    const int wn    = wid >> 1;
    const int lane8 = lane & 7;
    const int laneh = (lane >> 3) & 1;
    const int laneq = lane >> 4;

    const uint32_t sA0 = sbase;
    const uint32_t sB0 = sbase + NSTAGE * GBUF * 4;

    // per-lane ldmatrix offsets (bytes, within a buffer)
    const uint32_t a_lm =
        ((wm * 64 + lane8 + laneh * 8) * GS + laneq * 4) * 4;
    const uint32_t b_lm =
        ((wn * 32 + lane8) * GS + (lane >> 3) * 4) * 4;

    // Prologue: stages 0 and 1 in flight
    gemm_issue_loads(A, B, m0, n0, 0, sA0, sB0, tid);
    CP_COMMIT();
    gemm_issue_loads(A, B, m0, n0, 32, sA0 + GBUF * 4, sB0 + GBUF * 4, tid);
    CP_COMMIT();

    const int nk = CH / 32;
    int stage = 0;
    for (int ki = 0; ki < nk; ki++) {
        if (ki + 1 < nk) { CP_WAIT(1); } else { CP_WAIT(0); }
        __syncthreads();   // slab ki visible; all warps done with slab ki-1

        const uint32_t Ab = sA0 + stage * GBUF * 4;
        const uint32_t Bb = sB0 + stage * GBUF * 4;

        // A-fragment register double buffer: prefetch kq+1 while mma(kq).
        uint32_t af[2][4][4];
        uint32_t bf[4][4];
#pragma unroll
        for (int mt = 0; mt < 4; mt++)
            LDM_X4(af[0][mt], Ab + a_lm + mt * (16 * GS * 4));   // kq=0

#pragma unroll
        for (int kq = 0; kq < 4; kq++) {
            const int cur = kq & 1;
            if ((kq & 1) == 0) {
#pragma unroll
                for (int nt = 0; nt < 4; nt++)
                    LDM_X4(bf[nt], Bb + b_lm + nt * (8 * GS * 4) + (kq >> 1) * 64);
            }
            if (kq < 3) {
#pragma unroll
                for (int mt = 0; mt < 4; mt++)
                    LDM_X4(af[cur ^ 1][mt],
                           Ab + a_lm + mt * (16 * GS * 4) + (kq + 1) * 32);
            }
#pragma unroll
            for (int mt = 0; mt < 4; mt++)
#pragma unroll
                for (int nt = 0; nt < 4; nt++)
                    MMA_TF32(acc[mt][nt], af[cur][mt], &bf[nt][(kq & 1) * 2]);
        }

        // Refill the stage vacated at iteration ki-1 (compact burst — proven
        // faster than interleaving in round 8).
        if (ki + 2 < nk) {
            int ns = stage + 2 >= NSTAGE ? stage + 2 - NSTAGE : stage + 2;
            gemm_issue_loads(A, B, m0, n0, (ki + 2) * 32,
                             sA0 + ns * GBUF * 4, sB0 + ns * GBUF * 4, tid);
            CP_COMMIT();
        }
        stage = (stage + 1 == NSTAGE) ? 0 : stage + 1;
    }
}

// ---------------------------------------------------------------------------
// Kernel 1: QKV GEMM; writes q,k [b,h,t,d] and v [b,h,d,t], tf32-rounded,
// softmax scale folded into q.
// ---------------------------------------------------------------------------
__global__ __launch_bounds__(256, 2) void qkv_gemm_kernel(
    const float* __restrict__ bias)
{
    extern __shared__ float smg[];
    const uint32_t sbase = smem_u32(smg);
    const int tid = threadIdx.x;
    const int m0 = blockIdx.y * 128;
    const int n0 = blockIdx.x * 128;

    float acc[4][4][4];
#pragma unroll
    for (int i = 0; i < 4; i++)
#pragma unroll
        for (int j = 0; j < 4; j++)
#pragma unroll
            for (int q = 0; q < 4; q++) acc[i][j][q] = 0.f;

    tf32_gemm_tile(g_x, g_wa, m0, n0, acc, sbase, tid);

    const int lane = tid & 31;
    const int wid  = tid >> 5;
    const int wm   = wid & 1;
    const int wn   = wid >> 1;
    const int lr   = lane >> 2;
    const int lc   = lane & 3;

    const int sec = n0 >> 10;  // 0=q 1=k 2=v
    const float scale = (sec == 0) ? 0.125f : 1.0f;

#pragma unroll
    for (int mt = 0; mt < 4; mt++) {
        int r0 = m0 + wm * 64 + mt * 16 + lr;
        int bb = r0 >> 11;
        int t  = r0 & (SEQ - 1);
#pragma unroll
        for (int nt = 0; nt < 4; nt++) {
            int c0 = n0 + wn * 32 + nt * 8 + lc * 2;
            float b0 = bias[c0], b1 = bias[c0 + 1];
            int n1 = c0 & (CH - 1);
            int h  = n1 >> 6;
            int d  = n1 & 63;
            float v00 = to_tf32((acc[mt][nt][0] + b0) * scale);
            float v01 = to_tf32((acc[mt][nt][1] + b1) * scale);
            float v10 = to_tf32((acc[mt][nt][2] + b0) * scale);
            float v11 = to_tf32((acc[mt][nt][3] + b1) * scale);
            if (sec < 2) {
                float* dst = (sec == 0) ? g_q : g_k;
                size_t base = ((size_t)((bb * NHEAD + h) * SEQ + t)) * HDIM + d;
                *reinterpret_cast<float2*>(&dst[base]) = make_float2(v00, v01);
                *reinterpret_cast<float2*>(&dst[base + 8 * HDIM]) =
                    make_float2(v10, v11);
            } else {
                // v transposed: [b,h,d,t]
                size_t base = ((size_t)((bb * NHEAD + h) * HDIM + d)) * SEQ + t;
                g_v[base]           = v00;
                g_v[base + SEQ]     = v01;   // d+1
                g_v[base + 8]       = v10;   // t+8
                g_v[base + SEQ + 8] = v11;
            }
        }
    }
}

// ---------------------------------------------------------------------------
// Kernel 3: output projection
// ---------------------------------------------------------------------------
__global__ __launch_bounds__(256, 2) void proj_gemm_kernel(
    const float* __restrict__ bias, float* __restrict__ out)
{
    extern __shared__ float smg[];
    const uint32_t sbase = smem_u32(smg);
    const int tid = threadIdx.x;
    const int m0 = blockIdx.y * 128;
    const int n0 = blockIdx.x * 128;

    float acc[4][4][4];
#pragma unroll
    for (int i = 0; i < 4; i++)
#pragma unroll
        for (int j = 0; j < 4; j++)
#pragma unroll
            for (int q = 0; q < 4; q++) acc[i][j][q] = 0.f;

    tf32_gemm_tile(g_att, g_wp, m0, n0, acc, sbase, tid);

    const int lane = tid & 31;
    const int wid  = tid >> 5;
    const int wm   = wid & 1;
    const int wn   = wid >> 1;
    const int lr   = lane >> 2;
    const int lc   = lane & 3;

#pragma unroll
    for (int mt = 0; mt < 4; mt++) {
        int r0 = m0 + wm * 64 + mt * 16 + lr;
#pragma unroll
        for (int nt = 0; nt < 4; nt++) {
            int c0 = n0 + wn * 32 + nt * 8 + lc * 2;
            float b0 = bias[c0], b1 = bias[c0 + 1];
            *reinterpret_cast<float2*>(&out[(size_t)r0 * CH + c0]) =
                make_float2(acc[mt][nt][0] + b0, acc[mt][nt][1] + b1);
            *reinterpret_cast<float2*>(&out[(size_t)(r0 + 8) * CH + c0]) =
                make_float2(acc[mt][nt][2] + b0, acc[mt][nt][3] + b1);
        }
    }
}

// ---------------------------------------------------------------------------
// Kernel 2: causal flash attention, TF32 mma.sync + ldmatrix fragments,
// cp.async double-buffered K/V (round-7 structure: issue BEFORE wait,
// two barriers per tile — proven fastest).
// Block: 128 q x 64 kv; 8 warps x 16 q rows.
// ---------------------------------------------------------------------------
#define AST 68                     // attention smem row stride (floats)
#define KV_BUF (64 * AST)
#define ATTN_SMEM ((128 * AST + 4 * KV_BUF) * (int)sizeof(float))

__device__ __forceinline__ void attn_issue_kv(
    const float* __restrict__ kp, const float* __restrict__ vp,
    int k0, uint32_t sK, uint32_t sV, int tid)
{
#pragma unroll
    for (int it = 0; it < 4; it++) {
        int idx = it * 256 + tid;
        int row = idx >> 4;
        int c4  = (idx & 15) * 4;
        CP_ASYNC16(sK + row * (AST * 4) + c4 * 4,
                   kp + (size_t)(k0 + row) * HDIM + c4);
        CP_ASYNC16(sV + row * (AST * 4) + c4 * 4,
                   vp + (size_t)row * SEQ + k0 + c4);
    }
}

__global__ __launch_bounds__(256, 2) void attn_kernel()
{
    extern __shared__ float sm[];
    const uint32_t sbase = smem_u32(sm);
    const uint32_t sQs = sbase;
    const uint32_t sKs = sbase + 128 * AST * 4;
    const uint32_t sVs = sKs + 2 * KV_BUF * 4;

    const int tid   = threadIdx.x;
    const int lane  = tid & 31;
    const int wq    = tid >> 5;
    const int lr    = lane >> 2;
    const int lc    = lane & 3;
    const int lane8 = lane & 7;
    const int laneh = (lane >> 3) & 1;
    const int laneq = lane >> 4;

    const int qt = (int)gridDim.x - 1 - (int)blockIdx.x;  // big tiles first
    const int bh = blockIdx.y;
    const int q0 = qt * 128;

    const float* qp = g_q + (size_t)bh * SEQ * HDIM;
    const float* kp = g_k + (size_t)bh * SEQ * HDIM;
    const float* vp = g_v + (size_t)bh * HDIM * SEQ;

    const uint32_t q_lm = sQs +
        ((wq * 16 + lane8 + laneh * 8) * AST + laneq * 4) * 4;
    const uint32_t k_lm = (lane8 * AST + (lane >> 3) * 4) * 4;
    const uint32_t p_lm = ((lane8 + laneh * 8) * AST + laneq * 4) * 4;
    const uint32_t v_lm = ((laneq * 8 + lane8) * AST + laneh * 4) * 4;

#pragma unroll
    for (int it = 0; it < 8; it++) {
        int idx = it * 256 + tid;
        int row = idx >> 4;
        int c4  = (idx & 15) * 4;
        CP_ASYNC16(sQs + row * (AST * 4) + c4 * 4,
                   qp + (size_t)(q0 + row) * HDIM + c4);
    }
    attn_issue_kv(kp, vp, 0, sKs, sVs, tid);
    CP_COMMIT();

    uint32_t qf[8][4];
    const uint32_t sPt = sQs + wq * 16 * AST * 4;   // per-warp 16x64 slab
    float* Pt = sm + wq * 16 * AST;

    float o[8][4] = {};
    float m0v = -1e30f, m1v = -1e30f;
    float l0v = 0.f, l1v = 0.f;

    const int nkt  = 2 * qt + 2;
    const int r_hi = q0 + wq * 16 + 15;

    for (int kt = 0; kt < nkt; kt++) {
        const int k0 = kt * 64;
        if (kt + 1 < nkt) {
            attn_issue_kv(kp, vp, (kt + 1) * 64,
                          sKs + ((kt + 1) & 1) * KV_BUF * 4,
                          sVs + ((kt + 1) & 1) * KV_BUF * 4, tid);
            CP_COMMIT();
            CP_WAIT(1);
        } else {
            CP_WAIT(0);
        }
        __syncthreads();

        if (kt == 0) {
#pragma unroll
            for (int s = 0; s < 8; s++)
                LDM_X4(qf[s], q_lm + s * 32);
        }

        if (k0 <= r_hi) {
            const uint32_t Kb = sKs + (kt & 1) * KV_BUF * 4;
            const uint32_t Vb = sVs + (kt & 1) * KV_BUF * 4;

            float sacc[8][4];
#pragma unroll
            for (int nt = 0; nt < 8; nt++)
#pragma unroll
                for (int q = 0; q < 4; q++) sacc[nt][q] = 0.f;

#pragma unroll
            for (int s2 = 0; s2 < 4; s2++) {
                uint32_t bf[8][4];
#pragma unroll
                for (int nt = 0; nt < 8; nt++)
                    LDM_X4(bf[nt], Kb + k_lm + nt * (8 * AST * 4) + s2 * 64);
#pragma unroll
                for (int sub = 0; sub < 2; sub++)
#pragma unroll
                    for (int nt = 0; nt < 8; nt++)
                        MMA_TF32(sacc[nt], qf[2 * s2 + sub], &bf[nt][sub * 2]);
            }

            if (kt >= 2 * qt) {
                int r0g = q0 + wq * 16 + lr;
#pragma unroll
                for (int nt = 0; nt < 8; nt++) {
                    int c0g = k0 + nt * 8 + 2 * lc;
                    if (c0g     > r0g)     sacc[nt][0] = -1e30f;
                    if (c0g + 1 > r0g)     sacc[nt][1] = -1e30f;
                    if (c0g     > r0g + 8) sacc[nt][2] = -1e30f;
                    if (c0g + 1 > r0g + 8) sacc[nt][3] = -1e30f;
                }
            }

            float rm0 = -1e30f, rm1 = -1e30f;
#pragma unroll
            for (int nt = 0; nt < 8; nt++) {
                rm0 = fmaxf(rm0, fmaxf(sacc[nt][0], sacc[nt][1]));
                rm1 = fmaxf(rm1, fmaxf(sacc[nt][2], sacc[nt][3]));
            }
            rm0 = fmaxf(rm0, __shfl_xor_sync(0xffffffffu, rm0, 1));
            rm0 = fmaxf(rm0, __shfl_xor_sync(0xffffffffu, rm0, 2));
            rm1 = fmaxf(rm1, __shfl_xor_sync(0xffffffffu, rm1, 1));
            rm1 = fmaxf(rm1, __shfl_xor_sync(0xffffffffu, rm1, 2));

            float mn0 = fmaxf(m0v, rm0);
            float mn1 = fmaxf(m1v, rm1);
            float cr0 = __expf(m0v - mn0);
            float cr1 = __expf(m1v - mn1);
            m0v = mn0; m1v = mn1;

            float rs0 = 0.f, rs1 = 0.f;
#pragma unroll
            for (int nt = 0; nt < 8; nt++) {
                sacc[nt][0] = __expf(sacc[nt][0] - mn0);
                sacc[nt][1] = __expf(sacc[nt][1] - mn0);
                sacc[nt][2] = __expf(sacc[nt][2] - mn1);
                sacc[nt][3] = __expf(sacc[nt][3] - mn1);
                rs0 += sacc[nt][0] + sacc[nt][1];
                rs1 += sacc[nt][2] + sacc[nt][3];
            }
            rs0 += __shfl_xor_sync(0xffffffffu, rs0, 1);
            rs0 += __shfl_xor_sync(0xffffffffu, rs0, 2);
            rs1 += __shfl_xor_sync(0xffffffffu, rs1, 1);
            rs1 += __shfl_xor_sync(0xffffffffu, rs1, 2);
            l0v = l0v * cr0 + rs0;
            l1v = l1v * cr1 + rs1;
#pragma unroll
            for (int nt = 0; nt < 8; nt++) {
                o[nt][0] *= cr0; o[nt][1] *= cr0;
                o[nt][2] *= cr1; o[nt][3] *= cr1;
            }

#pragma unroll
            for (int nt = 0; nt < 8; nt++) {
                *reinterpret_cast<float2*>(&Pt[lr * AST + nt * 8 + 2 * lc]) =
                    make_float2(to_tf32(sacc[nt][0]), to_tf32(sacc[nt][1]));
                *reinterpret_cast<float2*>(&Pt[(lr + 8) * AST + nt * 8 + 2 * lc]) =
                    make_float2(to_tf32(sacc[nt][2]), to_tf32(sacc[nt][3]));
            }
            __syncwarp();

#pragma unroll
            for (int s = 0; s < 8; s++) {
                uint32_t a[4];
                LDM_X4(a, sPt + p_lm + s * 32);
#pragma unroll
                for (int dp = 0; dp < 4; dp++) {
                    uint32_t b[4];
                    LDM_X4(b, Vb + v_lm + dp * (16 * AST * 4) + s * 32);
                    MMA_TF32(o[2 * dp],     a, &b[0]);
                    MMA_TF32(o[2 * dp + 1], a, &b[2]);
                }
            }
            __syncwarp();
        }
        __syncthreads();
    }

    const int b = bh >> 4, h = bh & 15;
    const int r0g = q0 + wq * 16 + lr;
    const float inv0 = 1.0f / l0v;
    const float inv1 = 1.0f / l1v;
#pragma unroll
    for (int nt = 0; nt < 8; nt++) {
        int cg = h * 64 + nt * 8 + 2 * lc;
        *reinterpret_cast<float2*>(&g_att[(size_t)(b * SEQ + r0g) * CH + cg]) =
            make_float2(to_tf32(o[nt][0] * inv0), to_tf32(o[nt][1] * inv0));
        *reinterpret_cast<float2*>(&g_att[(size_t)(b * SEQ + r0g + 8) * CH + cg]) =
            make_float2(to_tf32(o[nt][2] * inv1), to_tf32(o[nt][3] * inv1));
    }
}

// ---------------------------------------------------------------------------
extern "C" void kernel_launch(void* const* d_in, const int* in_sizes, int n_in,
                              void* d_out, int out_size)
{
    const float* x      = (const float*)d_in[0];
    const float* w_attn = (const float*)d_in[1];
    const float* b_attn = (const float*)d_in[2];
    const float* w_proj = (const float*)d_in[3];
    const float* b_proj = (const float*)d_in[4];
    float* out = (float*)d_out;

    cudaFuncSetAttribute(qkv_gemm_kernel,
                         cudaFuncAttributeMaxDynamicSharedMemorySize, GEMM_SMEM);
    cudaFuncSetAttribute(proj_gemm_kernel,
                         cudaFuncAttributeMaxDynamicSharedMemorySize, GEMM_SMEM);
    cudaFuncSetAttribute(attn_kernel,
                         cudaFuncAttributeMaxDynamicSharedMemorySize, ATTN_SMEM);

    // 0) tf32-round x; transpose+round weights to [N][K]
    cvt_x_kernel<<<(BATCH * SEQ * CH / 4 + 255) / 256, 256>>>(x,
        BATCH * SEQ * CH / 4);
    cvt_T_kernel<<<dim3(3 * CH / 32, CH / 32), dim3(32, 8)>>>(w_attn, 1, 3 * CH);
    cvt_T_kernel<<<dim3(CH / 32, CH / 32), dim3(32, 8)>>>(w_proj, 2, CH);

    // 1) QKV GEMM: grid (3072/128, 8192/128)
    qkv_gemm_kernel<<<dim3(24, 64), 256, GEMM_SMEM>>>(b_attn);

    // 2) Attention: grid (16 q-tiles, B*NH)
    attn_kernel<<<dim3(16, BATCH * NHEAD), 256, ATTN_SMEM>>>();

    // 3) Projection: grid (1024/128, 8192/128)
    proj_gemm_kernel<<<dim3(8, 64), 256, GEMM_SMEM>>>(b_proj, out);
}

// round 10
// speedup vs baseline: 1.0809x; 1.0066x over previous
#include <cuda_runtime.h>
#include <cstdint>

#define BATCH 4
#define SEQ   2048
#define CH    1024
#define NHEAD 16
#define HDIM  64

// Scratch (allocation-free rule: __device__ globals).
// q,k: [b,h,t,d]; v: [b,h,d,t] (transposed for PV ldmatrix).
__device__ float g_q[BATCH * NHEAD * SEQ * HDIM];
__device__ float g_k[BATCH * NHEAD * SEQ * HDIM];
__device__ float g_v[BATCH * NHEAD * HDIM * SEQ];
__device__ float g_att[BATCH * SEQ * CH];        // [b,t,c], tf32-rounded
__device__ float g_x [BATCH * SEQ * CH];         // x, tf32-rounded
__device__ float g_wa[3 * CH * CH];              // w_attn^T: [3072][1024], tf32
__device__ float g_wp[CH * CH];                  // w_proj^T: [1024][1024], tf32

__device__ __forceinline__ float to_tf32(float x) {
    float r;
    asm("cvt.rna.tf32.f32 %0, %1;" : "=f"(r) : "f"(x));
    return r;
}

#define MMA_TF32(d, a, b)                                                  \
    asm volatile(                                                          \
        "mma.sync.aligned.m16n8k8.row.col.f32.tf32.tf32.f32 "              \
        "{%0,%1,%2,%3},{%4,%5,%6,%7},{%8,%9},{%0,%1,%2,%3};"               \
        : "+f"((d)[0]), "+f"((d)[1]), "+f"((d)[2]), "+f"((d)[3])           \
        : "r"((a)[0]), "r"((a)[1]), "r"((a)[2]), "r"((a)[3]),              \
          "r"((b)[0]), "r"((b)[1]))

// ldmatrix x4 on b16 8x8 tiles == 8x4 fp32 blocks (tf32 fragment layout).
#define LDM_X4(r, addr)                                                    \
    asm volatile("ldmatrix.sync.aligned.m8n8.x4.shared.b16 "               \
                 "{%0,%1,%2,%3}, [%4];"                                    \
                 : "=r"((r)[0]), "=r"((r)[1]), "=r"((r)[2]), "=r"((r)[3])  \
                 : "r"(addr))

#define CP_ASYNC16(dst_u32, src_ptr)                                       \
    asm volatile("cp.async.cg.shared.global [%0], [%1], 16;"               \
                 :: "r"(dst_u32), "l"(src_ptr))
#define CP_COMMIT() asm volatile("cp.async.commit_group;")
#define CP_WAIT(N)  asm volatile("cp.async.wait_group %0;" :: "n"(N))

// ---- mbarrier helpers (sm_90 PTX, compiles for compute_103) ----
#define MBAR_INIT(addr, cnt)                                               \
    asm volatile("mbarrier.init.shared::cta.b64 [%0], %1;"                 \
                 :: "r"(addr), "r"((uint32_t)(cnt)) : "memory")
#define MBAR_ARRIVE(addr)                                                  \
    asm volatile("{\n\t.reg .b64 t;\n\t"                                   \
                 "mbarrier.arrive.shared::cta.b64 t, [%0];\n\t}"           \
                 :: "r"(addr) : "memory")
#define CPA_MBAR_ARRIVE(addr)                                              \
    asm volatile("cp.async.mbarrier.arrive.noinc.shared::cta.b64 [%0];"    \
                 :: "r"(addr) : "memory")

__device__ __forceinline__ void mbar_wait(uint32_t mbar, uint32_t parity) {
    asm volatile(
        "{\n\t.reg .pred P;\n\t"
        "W_%=:\n\t"
        "mbarrier.try_wait.parity.acquire.cta.shared::cta.b64 P, [%0], %1, 0x989680;\n\t"
        "@!P bra W_%=;\n\t"
        "}" :: "r"(mbar), "r"(parity) : "memory");
}

__device__ __forceinline__ uint32_t smem_u32(const void* p) {
    return (uint32_t)__cvta_generic_to_shared(p);
}

// ---------------------------------------------------------------------------
// Prologue converts
// ---------------------------------------------------------------------------
__global__ void cvt_x_kernel(const float* __restrict__ src, int n4)
{
    int i = blockIdx.x * blockDim.x + threadIdx.x;
    if (i < n4) {
        float4 v = reinterpret_cast<const float4*>(src)[i];
        v.x = to_tf32(v.x); v.y = to_tf32(v.y);
        v.z = to_tf32(v.z); v.w = to_tf32(v.w);
        reinterpret_cast<float4*>(g_x)[i] = v;
    }
}

// Transpose + tf32-round weights: src [CH][N] -> dst [N][CH]
__global__ void cvt_T_kernel(const float* __restrict__ src, int sel, int N)
{
    __shared__ float tile[32][33];
    float* dst = (sel == 1) ? g_wa : g_wp;
    int n0 = blockIdx.x * 32, k0 = blockIdx.y * 32;
    int tx = threadIdx.x, ty = threadIdx.y;  // 32 x 8
#pragma unroll
    for (int i = 0; i < 4; i++)
        tile[ty + 8 * i][tx] = src[(size_t)(k0 + ty + 8 * i) * N + n0 + tx];
    __syncthreads();
#pragma unroll
    for (int i = 0; i < 4; i++)
        dst[(size_t)(n0 + ty + 8 * i) * CH + k0 + tx] = to_tf32(tile[tx][ty + 8 * i]);
}

// ---------------------------------------------------------------------------
// TF32 GEMM core (round-9 best): 128x128 block, BK=32, 8 warps (2x4),
// 3-stage cp.async pipeline + register double-buffered A fragments.
// ---------------------------------------------------------------------------
#define GS 36
#define GBUF (128 * GS)
#define NSTAGE 3
#define GEMM_SMEM (2 * NSTAGE * GBUF * (int)sizeof(float))   // 110592 B

__device__ __forceinline__ void gemm_issue_loads(
    const float* __restrict__ A, const float* __restrict__ B,
    int m0, int n0, int k0, uint32_t sA, uint32_t sB, int tid)
{
#pragma unroll
    for (int it = 0; it < 4; it++) {
        int idx = it * 256 + tid;
        int row = idx >> 3, c = idx & 7;
        CP_ASYNC16(sA + row * (GS * 4) + c * 16,
                   A + (size_t)(m0 + row) * CH + k0 + c * 4);
    }
#pragma unroll
    for (int it = 0; it < 4; it++) {
        int idx = it * 256 + tid;
        int row = idx >> 3, c = idx & 7;
        CP_ASYNC16(sB + row * (GS * 4) + c * 16,
                   B + (size_t)(n0 + row) * CH + k0 + c * 4);
    }
}

__device__ __forceinline__ void tf32_gemm_tile(
    const float* __restrict__ A, const float* __restrict__ B,
    int m0, int n0,
    float acc[4][4][4],
    uint32_t sbase, int tid)
{
    const int lane  = tid & 31;
    const int wid   = tid >> 5;
    const int wm    = wid & 1;
    const int wn    = wid >> 1;
    const int lane8 = lane & 7;
    const int laneh = (lane >> 3) & 1;
    const int laneq = lane >> 4;

    const uint32_t sA0 = sbase;
    const uint32_t sB0 = sbase + NSTAGE * GBUF * 4;

    const uint32_t a_lm =
        ((wm * 64 + lane8 + laneh * 8) * GS + laneq * 4) * 4;
    const uint32_t b_lm =
        ((wn * 32 + lane8) * GS + (lane >> 3) * 4) * 4;

    gemm_issue_loads(A, B, m0, n0, 0, sA0, sB0, tid);
    CP_COMMIT();
    gemm_issue_loads(A, B, m0, n0, 32, sA0 + GBUF * 4, sB0 + GBUF * 4, tid);
    CP_COMMIT();

    const int nk = CH / 32;
    int stage = 0;
    for (int ki = 0; ki < nk; ki++) {
        if (ki + 1 < nk) { CP_WAIT(1); } else { CP_WAIT(0); }
        __syncthreads();

        const uint32_t Ab = sA0 + stage * GBUF * 4;
        const uint32_t Bb = sB0 + stage * GBUF * 4;

        uint32_t af[2][4][4];
        uint32_t bf[4][4];
#pragma unroll
        for (int mt = 0; mt < 4; mt++)
            LDM_X4(af[0][mt], Ab + a_lm + mt * (16 * GS * 4));

#pragma unroll
        for (int kq = 0; kq < 4; kq++) {
            const int cur = kq & 1;
            if ((kq & 1) == 0) {
#pragma unroll
                for (int nt = 0; nt < 4; nt++)
                    LDM_X4(bf[nt], Bb + b_lm + nt * (8 * GS * 4) + (kq >> 1) * 64);
            }
            if (kq < 3) {
#pragma unroll
                for (int mt = 0; mt < 4; mt++)
                    LDM_X4(af[cur ^ 1][mt],
                           Ab + a_lm + mt * (16 * GS * 4) + (kq + 1) * 32);
            }
#pragma unroll
            for (int mt = 0; mt < 4; mt++)
#pragma unroll
                for (int nt = 0; nt < 4; nt++)
                    MMA_TF32(acc[mt][nt], af[cur][mt], &bf[nt][(kq & 1) * 2]);
        }

        if (ki + 2 < nk) {
            int ns = stage + 2 >= NSTAGE ? stage + 2 - NSTAGE : stage + 2;
            gemm_issue_loads(A, B, m0, n0, (ki + 2) * 32,
                             sA0 + ns * GBUF * 4, sB0 + ns * GBUF * 4, tid);
            CP_COMMIT();
        }
        stage = (stage + 1 == NSTAGE) ? 0 : stage + 1;
    }
}

// ---------------------------------------------------------------------------
// Kernel 1: QKV GEMM; writes q,k [b,h,t,d] and v [b,h,d,t], tf32-rounded,
// softmax scale folded into q.
// ---------------------------------------------------------------------------
__global__ __launch_bounds__(256, 2) void qkv_gemm_kernel(
    const float* __restrict__ bias)
{
    extern __shared__ float smg[];
    const uint32_t sbase = smem_u32(smg);
    const int tid = threadIdx.x;
    const int m0 = blockIdx.y * 128;
    const int n0 = blockIdx.x * 128;

    float acc[4][4][4];
#pragma unroll
    for (int i = 0; i < 4; i++)
#pragma unroll
        for (int j = 0; j < 4; j++)
#pragma unroll
            for (int q = 0; q < 4; q++) acc[i][j][q] = 0.f;

    tf32_gemm_tile(g_x, g_wa, m0, n0, acc, sbase, tid);

    const int lane = tid & 31;
    const int wid  = tid >> 5;
    const int wm   = wid & 1;
    const int wn   = wid >> 1;
    const int lr   = lane >> 2;
    const int lc   = lane & 3;

    const int sec = n0 >> 10;  // 0=q 1=k 2=v
    const float scale = (sec == 0) ? 0.125f : 1.0f;

#pragma unroll
    for (int mt = 0; mt < 4; mt++) {
        int r0 = m0 + wm * 64 + mt * 16 + lr;
        int bb = r0 >> 11;
        int t  = r0 & (SEQ - 1);
#pragma unroll
        for (int nt = 0; nt < 4; nt++) {
            int c0 = n0 + wn * 32 + nt * 8 + lc * 2;
            float b0 = bias[c0], b1 = bias[c0 + 1];
            int n1 = c0 & (CH - 1);
            int h  = n1 >> 6;
            int d  = n1 & 63;
            float v00 = to_tf32((acc[mt][nt][0] + b0) * scale);
            float v01 = to_tf32((acc[mt][nt][1] + b1) * scale);
            float v10 = to_tf32((acc[mt][nt][2] + b0) * scale);
            float v11 = to_tf32((acc[mt][nt][3] + b1) * scale);
            if (sec < 2) {
                float* dst = (sec == 0) ? g_q : g_k;
                size_t base = ((size_t)((bb * NHEAD + h) * SEQ + t)) * HDIM + d;
                *reinterpret_cast<float2*>(&dst[base]) = make_float2(v00, v01);
                *reinterpret_cast<float2*>(&dst[base + 8 * HDIM]) =
                    make_float2(v10, v11);
            } else {
                size_t base = ((size_t)((bb * NHEAD + h) * HDIM + d)) * SEQ + t;
                g_v[base]           = v00;
                g_v[base + SEQ]     = v01;   // d+1
                g_v[base + 8]       = v10;   // t+8
                g_v[base + SEQ + 8] = v11;
            }
        }
    }
}

// ---------------------------------------------------------------------------
// Kernel 3: output projection
// ---------------------------------------------------------------------------
__global__ __launch_bounds__(256, 2) void proj_gemm_kernel(
    const float* __restrict__ bias, float* __restrict__ out)
{
    extern __shared__ float smg[];
    const uint32_t sbase = smem_u32(smg);
    const int tid = threadIdx.x;
    const int m0 = blockIdx.y * 128;
    const int n0 = blockIdx.x * 128;

    float acc[4][4][4];
#pragma unroll
    for (int i = 0; i < 4; i++)
#pragma unroll
        for (int j = 0; j < 4; j++)
#pragma unroll
            for (int q = 0; q < 4; q++) acc[i][j][q] = 0.f;

    tf32_gemm_tile(g_att, g_wp, m0, n0, acc, sbase, tid);

    const int lane = tid & 31;
    const int wid  = tid >> 5;
    const int wm   = wid & 1;
    const int wn   = wid >> 1;
    const int lr   = lane >> 2;
    const int lc   = lane & 3;

#pragma unroll
    for (int mt = 0; mt < 4; mt++) {
        int r0 = m0 + wm * 64 + mt * 16 + lr;
#pragma unroll
        for (int nt = 0; nt < 4; nt++) {
            int c0 = n0 + wn * 32 + nt * 8 + lc * 2;
            float b0 = bias[c0], b1 = bias[c0 + 1];
            *reinterpret_cast<float2*>(&out[(size_t)r0 * CH + c0]) =
                make_float2(acc[mt][nt][0] + b0, acc[mt][nt][1] + b1);
            *reinterpret_cast<float2*>(&out[(size_t)(r0 + 8) * CH + c0]) =
                make_float2(acc[mt][nt][2] + b0, acc[mt][nt][3] + b1);
        }
    }
}

// ---------------------------------------------------------------------------
// Kernel 2: causal flash attention, TF32 mma.sync + ldmatrix fragments.
// NEW: mbarrier producer/consumer K/V pipeline with warp skew tolerance 1:
//   full[s]  : 256 x cp.async.mbarrier.arrive.noinc (tile data complete)
//   empty[s] : 8 warp arrivals (all warps done reading the tile)
// Per iteration j, a warp first (if j>=1, j+1<nkt) waits empty of stage
// (j+1)&1 for the cycle of tile j-1, issues its slice of tile j+1, then
// waits full[j], computes, arrives empty[j]. No __syncthreads in the loop:
// warps may skew by one tile, interleaving softmax and mma across warps.
// ---------------------------------------------------------------------------
#define AST 68
#define KV_BUF (64 * AST)
#define ATTN_SMEM (((128 * AST + 4 * KV_BUF) * 4) + 32)

__device__ __forceinline__ void attn_issue_kv(
    const float* __restrict__ kp, const float* __restrict__ vp,
    int k0, uint32_t sK, uint32_t sV, int tid)
{
#pragma unroll
    for (int it = 0; it < 4; it++) {
        int idx = it * 256 + tid;
        int row = idx >> 4;
        int c4  = (idx & 15) * 4;
        CP_ASYNC16(sK + row * (AST * 4) + c4 * 4,
                   kp + (size_t)(k0 + row) * HDIM + c4);
        CP_ASYNC16(sV + row * (AST * 4) + c4 * 4,
                   vp + (size_t)row * SEQ + k0 + c4);
    }
}

__global__ __launch_bounds__(256, 2) void attn_kernel()
{
    extern __shared__ float sm[];
    const uint32_t sbase = smem_u32(sm);
    const uint32_t sQs = sbase;
    const uint32_t sKs = sbase + 128 * AST * 4;
    const uint32_t sVs = sKs + 2 * KV_BUF * 4;
    const uint32_t mbF = sVs + 2 * KV_BUF * 4;   // full0, full1
    const uint32_t mbE = mbF + 16;               // empty0, empty1

    const int tid   = threadIdx.x;
    const int lane  = tid & 31;
    const int wq    = tid >> 5;
    const int lr    = lane >> 2;
    const int lc    = lane & 3;
    const int lane8 = lane & 7;
    const int laneh = (lane >> 3) & 1;
    const int laneq = lane >> 4;

    const int qt = (int)gridDim.x - 1 - (int)blockIdx.x;  // big tiles first
    const int bh = blockIdx.y;
    const int q0 = qt * 128;

    const float* qp = g_q + (size_t)bh * SEQ * HDIM;
    const float* kp = g_k + (size_t)bh * SEQ * HDIM;
    const float* vp = g_v + (size_t)bh * HDIM * SEQ;

    const uint32_t q_lm = sQs +
        ((wq * 16 + lane8 + laneh * 8) * AST + laneq * 4) * 4;
    const uint32_t k_lm = (lane8 * AST + (lane >> 3) * 4) * 4;
    const uint32_t p_lm = ((lane8 + laneh * 8) * AST + laneq * 4) * 4;
    const uint32_t v_lm = ((laneq * 8 + lane8) * AST + laneh * 4) * 4;

    if (tid == 0) {
        MBAR_INIT(mbF + 0, 256);
        MBAR_INIT(mbF + 8, 256);
        MBAR_INIT(mbE + 0, 8);
        MBAR_INIT(mbE + 8, 8);
    }
    __syncthreads();

    // Prologue: Q tile + kv tiles 0 and 1 (nkt >= 2 always).
#pragma unroll
    for (int it = 0; it < 8; it++) {
        int idx = it * 256 + tid;
        int row = idx >> 4;
        int c4  = (idx & 15) * 4;
        CP_ASYNC16(sQs + row * (AST * 4) + c4 * 4,
                   qp + (size_t)(q0 + row) * HDIM + c4);
    }
    attn_issue_kv(kp, vp, 0, sKs, sVs, tid);
    CPA_MBAR_ARRIVE(mbF + 0);          // covers Q + tile 0
    attn_issue_kv(kp, vp, 64, sKs + KV_BUF * 4, sVs + KV_BUF * 4, tid);
    CPA_MBAR_ARRIVE(mbF + 8);          // covers tile 1 (and priors)

    uint32_t qf[8][4];
    const uint32_t sPt = sQs + wq * 16 * AST * 4;   // per-warp 16x64 slab
    float* Pt = sm + wq * 16 * AST;

    float o[8][4] = {};
    float m0v = -1e30f, m1v = -1e30f;
    float l0v = 0.f, l1v = 0.f;

    const int nkt  = 2 * qt + 2;
    const int r_hi = q0 + wq * 16 + 15;

    for (int kt = 0; kt < nkt; kt++) {
        const int k0 = kt * 64;
        const uint32_t s  = (uint32_t)(kt & 1);
        const uint32_t cp = (uint32_t)((kt >> 1) & 1);

        // Produce tile kt+1 into stage s^1 (needs all warps done with kt-1).
        if (kt >= 1 && kt + 1 < nkt) {
            const uint32_t so = s ^ 1u;
            mbar_wait(mbE + so * 8, (uint32_t)(((kt - 1) >> 1) & 1));
            attn_issue_kv(kp, vp, (kt + 1) * 64,
                          sKs + so * KV_BUF * 4, sVs + so * KV_BUF * 4, tid);
            CPA_MBAR_ARRIVE(mbF + so * 8);
        }

        // Consume tile kt.
        mbar_wait(mbF + s * 8, cp);

        if (kt == 0) {
#pragma unroll
            for (int ss = 0; ss < 8; ss++)
                LDM_X4(qf[ss], q_lm + ss * 32);
        }

        if (k0 <= r_hi) {
            const uint32_t Kb = sKs + s * KV_BUF * 4;
            const uint32_t Vb = sVs + s * KV_BUF * 4;

            float sacc[8][4];
#pragma unroll
            for (int nt = 0; nt < 8; nt++)
#pragma unroll
                for (int q = 0; q < 4; q++) sacc[nt][q] = 0.f;

#pragma unroll
            for (int s2 = 0; s2 < 4; s2++) {
                uint32_t bf[8][4];
#pragma unroll
                for (int nt = 0; nt < 8; nt++)
                    LDM_X4(bf[nt], Kb + k_lm + nt * (8 * AST * 4) + s2 * 64);
#pragma unroll
                for (int sub = 0; sub < 2; sub++)
#pragma unroll
                    for (int nt = 0; nt < 8; nt++)
                        MMA_TF32(sacc[nt], qf[2 * s2 + sub], &bf[nt][sub * 2]);
            }

            if (kt >= 2 * qt) {
                int r0g = q0 + wq * 16 + lr;
#pragma unroll
                for (int nt = 0; nt < 8; nt++) {
                    int c0g = k0 + nt * 8 + 2 * lc;
                    if (c0g     > r0g)     sacc[nt][0] = -1e30f;
                    if (c0g + 1 > r0g)     sacc[nt][1] = -1e30f;
                    if (c0g     > r0g + 8) sacc[nt][2] = -1e30f;
                    if (c0g + 1 > r0g + 8) sacc[nt][3] = -1e30f;
                }
            }

            float rm0 = -1e30f, rm1 = -1e30f;
#pragma unroll
            for (int nt = 0; nt < 8; nt++) {
                rm0 = fmaxf(rm0, fmaxf(sacc[nt][0], sacc[nt][1]));
                rm1 = fmaxf(rm1, fmaxf(sacc[nt][2], sacc[nt][3]));
            }
            rm0 = fmaxf(rm0, __shfl_xor_sync(0xffffffffu, rm0, 1));
            rm0 = fmaxf(rm0, __shfl_xor_sync(0xffffffffu, rm0, 2));
            rm1 = fmaxf(rm1, __shfl_xor_sync(0xffffffffu, rm1, 1));
            rm1 = fmaxf(rm1, __shfl_xor_sync(0xffffffffu, rm1, 2));

            float mn0 = fmaxf(m0v, rm0);
            float mn1 = fmaxf(m1v, rm1);
            float cr0 = __expf(m0v - mn0);
            float cr1 = __expf(m1v - mn1);
            m0v = mn0; m1v = mn1;

            float rs0 = 0.f, rs1 = 0.f;
#pragma unroll
            for (int nt = 0; nt < 8; nt++) {
                sacc[nt][0] = __expf(sacc[nt][0] - mn0);
                sacc[nt][1] = __expf(sacc[nt][1] - mn0);
                sacc[nt][2] = __expf(sacc[nt][2] - mn1);
                sacc[nt][3] = __expf(sacc[nt][3] - mn1);
                rs0 += sacc[nt][0] + sacc[nt][1];
                rs1 += sacc[nt][2] + sacc[nt][3];
            }
            rs0 += __shfl_xor_sync(0xffffffffu, rs0, 1);
            rs0 += __shfl_xor_sync(0xffffffffu, rs0, 2);
            rs1 += __shfl_xor_sync(0xffffffffu, rs1, 1);
            rs1 += __shfl_xor_sync(0xffffffffu, rs1, 2);
            l0v = l0v * cr0 + rs0;
            l1v = l1v * cr1 + rs1;
#pragma unroll
            for (int nt = 0; nt < 8; nt++) {
                o[nt][0] *= cr0; o[nt][1] *= cr0;
                o[nt][2] *= cr1; o[nt][3] *= cr1;
            }

#pragma unroll
            for (int nt = 0; nt < 8; nt++) {
                *reinterpret_cast<float2*>(&Pt[lr * AST + nt * 8 + 2 * lc]) =
                    make_float2(to_tf32(sacc[nt][0]), to_tf32(sacc[nt][1]));
                *reinterpret_cast<float2*>(&Pt[(lr + 8) * AST + nt * 8 + 2 * lc]) =
                    make_float2(to_tf32(sacc[nt][2]), to_tf32(sacc[nt][3]));
            }
            __syncwarp();

#pragma unroll
            for (int ss = 0; ss < 8; ss++) {
                uint32_t a[4];
                LDM_X4(a, sPt + p_lm + ss * 32);
#pragma unroll
                for (int dp = 0; dp < 4; dp++) {
                    uint32_t b[4];
                    LDM_X4(b, Vb + v_lm + dp * (16 * AST * 4) + ss * 32);
                    MMA_TF32(o[2 * dp],     a, &b[0]);
                    MMA_TF32(o[2 * dp + 1], a, &b[2]);
                }
            }
        }

        __syncwarp();
        if (lane == 0) MBAR_ARRIVE(mbE + s * 8);   // done reading tile kt
    }

    const int b = bh >> 4, h = bh & 15;
    const int r0g = q0 + wq * 16 + lr;
    const float inv0 = 1.0f / l0v;
    const float inv1 = 1.0f / l1v;
#pragma unroll
    for (int nt = 0; nt < 8; nt++) {
        int cg = h * 64 + nt * 8 + 2 * lc;
        *reinterpret_cast<float2*>(&g_att[(size_t)(b * SEQ + r0g) * CH + cg]) =
            make_float2(to_tf32(o[nt][0] * inv0), to_tf32(o[nt][1] * inv0));
        *reinterpret_cast<float2*>(&g_att[(size_t)(b * SEQ + r0g + 8) * CH + cg]) =
            make_float2(to_tf32(o[nt][2] * inv1), to_tf32(o[nt][3] * inv1));
    }
}

// ---------------------------------------------------------------------------
extern "C" void kernel_launch(void* const* d_in, const int* in_sizes, int n_in,
                              void* d_out, int out_size)
{
    const float* x      = (const float*)d_in[0];
    const float* w_attn = (const float*)d_in[1];
    const float* b_attn = (const float*)d_in[2];
    const float* w_proj = (const float*)d_in[3];
    const float* b_proj = (const float*)d_in[4];
    float* out = (float*)d_out;

    cudaFuncSetAttribute(qkv_gemm_kernel,
                         cudaFuncAttributeMaxDynamicSharedMemorySize, GEMM_SMEM);
    cudaFuncSetAttribute(proj_gemm_kernel,
                         cudaFuncAttributeMaxDynamicSharedMemorySize, GEMM_SMEM);
    cudaFuncSetAttribute(attn_kernel,
                         cudaFuncAttributeMaxDynamicSharedMemorySize, ATTN_SMEM);

    // 0) tf32-round x; transpose+round weights to [N][K]
    cvt_x_kernel<<<(BATCH * SEQ * CH / 4 + 255) / 256, 256>>>(x,
        BATCH * SEQ * CH / 4);
    cvt_T_kernel<<<dim3(3 * CH / 32, CH / 32), dim3(32, 8)>>>(w_attn, 1, 3 * CH);
    cvt_T_kernel<<<dim3(CH / 32, CH / 32), dim3(32, 8)>>>(w_proj, 2, CH);

    // 1) QKV GEMM: grid (3072/128, 8192/128)
    qkv_gemm_kernel<<<dim3(24, 64), 256, GEMM_SMEM>>>(b_attn);

    // 2) Attention: grid (16 q-tiles, B*NH)
    attn_kernel<<<dim3(16, BATCH * NHEAD), 256, ATTN_SMEM>>>();

    // 3) Projection: grid (1024/128, 8192/128)
    proj_gemm_kernel<<<dim3(8, 64), 256, GEMM_SMEM>>>(b_proj, out);
}